// round 9
// baseline (speedup 1.0000x reference)
#include <cuda_runtime.h>
#include <cstdint>

#define BB 2
#define SS 2048
#define DD 1024
#define HH 16
#define EHD 64
#define MM (BB*SS)   // 4096

__device__ float g_wq[DD*DD];
__device__ float g_wk[DD*DD];
__device__ float g_wv[DD*DD];
__device__ float g_e [MM*DD];   // tf32-rounded E
__device__ float g_wo[DD*DD];   // tf32-rounded WO
__device__ float g_q[MM*DD];
__device__ float g_k[MM*DD];
__device__ float g_v[MM*DD];
__device__ float g_o[MM*DD];

__device__ __forceinline__ uint32_t f2tf(float x) {
    uint32_t u; asm("cvt.rna.tf32.f32 %0, %1;" : "=r"(u) : "f"(x)); return u;
}

template<bool DOCVT>
__device__ __forceinline__ uint4 pack4(float4 v) {
    if (DOCVT)
        return make_uint4(f2tf(v.x), f2tf(v.y), f2tf(v.z), f2tf(v.w));
    return make_uint4(__float_as_uint(v.x), __float_as_uint(v.y),
                      __float_as_uint(v.z), __float_as_uint(v.w));
}

__device__ __forceinline__ uint32_t smem_u32(const void* p) {
    uint32_t a;
    asm("{ .reg .u64 t; cvta.to.shared.u64 t, %1; cvt.u32.u64 %0, t; }"
        : "=r"(a) : "l"(p));
    return a;
}

__device__ __forceinline__ void ldsm4(uint32_t* d, uint32_t addr) {
    asm volatile("ldmatrix.sync.aligned.m8n8.x4.shared.b16 {%0,%1,%2,%3}, [%4];"
        : "=r"(d[0]), "=r"(d[1]), "=r"(d[2]), "=r"(d[3]) : "r"(addr));
}

__device__ __forceinline__ void mma8(float* d, const uint32_t* a, const uint32_t* b) {
    asm volatile("mma.sync.aligned.m16n8k8.row.col.f32.tf32.tf32.f32 "
        "{%0,%1,%2,%3}, {%4,%5,%6,%7}, {%8,%9}, {%0,%1,%2,%3};\n"
        : "+f"(d[0]), "+f"(d[1]), "+f"(d[2]), "+f"(d[3])
        : "r"(a[0]), "r"(a[1]), "r"(a[2]), "r"(a[3]), "r"(b[0]), "r"(b[1]));
}

__device__ __forceinline__ void cp_async16(uint32_t saddr, const void* gaddr) {
    asm volatile("cp.async.ca.shared.global [%0], [%1], 16;"
                 :: "r"(saddr), "l"(gaddr) : "memory");
}
__device__ __forceinline__ void cp_commit() {
    asm volatile("cp.async.commit_group;" ::: "memory");
}

struct GemmBatch {
    const float* A[3];
    const float* B[3];
    float*       C[3];
};

// ---------------------------------------------------------------------------
// Elementwise tf32 rounding (producer for the cp.async GEMMs)
// ---------------------------------------------------------------------------
__global__ void round_tf32(const float* __restrict__ s, float* __restrict__ d, int n4)
{
    int i = blockIdx.x * blockDim.x + threadIdx.x;
    if (i < n4) {
        float4 v = ((const float4*)s)[i];
        ((uint4*)d)[i] = pack4<true>(v);
    }
}

// ---------------------------------------------------------------------------
// Weight-prep GEMM (NN): C = A[M,K] @ B[K,N], register-path 2-stage buffer.
// A,B external fp32 -> cvt; C stored tf32-rounded. Small (192 CTAs total).
// ---------------------------------------------------------------------------
__global__ __launch_bounds__(256) void gemm_nn(GemmBatch gb, int M, int N, int K)
{
    __shared__ uint32_t As[2][128][20];
    __shared__ uint32_t Bs[2][128][20];
    const float* __restrict__ A  = gb.A[blockIdx.z];
    const float* __restrict__ Bm = gb.B[blockIdx.z];
    float* __restrict__ C        = gb.C[blockIdx.z];

    const int tid  = threadIdx.x;
    const int lane = tid & 31, wid = tid >> 5;
    const int wm = wid & 3, wn = wid >> 2;
    const int m0 = blockIdx.y * 128, n0 = blockIdx.x * 128;
    const int r = lane >> 2, c = lane & 3;

    const int l15   = lane & 15;
    const int khalf = (lane >> 4) & 1;
    const int b_r   = (lane & 7) + ((lane & 16) >> 1);
    const int b_k4  = (lane & 8) >> 1;

    const uint32_t As_base = smem_u32(&As[0][0][0]);
    const uint32_t Bs_base = smem_u32(&Bs[0][0][0]);
    const uint32_t BUFB = 128 * 20 * 4;
    const uint32_t a_addr0 = As_base + (((wm * 32 + l15) * 20 + 4 * khalf) << 2);
    const uint32_t b_addr0 = Bs_base + (((wn * 64 + b_r) * 20 + b_k4) << 2);

    const int arow = tid >> 2, akq = (tid & 3) * 4;
    const int bkk  = tid & 15, bc4 = tid >> 4;

    float acc[2][8][4] = {};
    float4 pa[2], pb[2];

    auto ldg_tile = [&](int k0) {
        pa[0] = *(const float4*)&A[(size_t)(m0 + arow) * K + k0 + akq];
        pa[1] = *(const float4*)&A[(size_t)(m0 + arow + 64) * K + k0 + akq];
        pb[0] = *(const float4*)&Bm[(size_t)(k0 + bkk) * N + n0 + bc4 * 4];
        pb[1] = *(const float4*)&Bm[(size_t)(k0 + bkk) * N + n0 + (bc4 + 16) * 4];
    };
    auto sts_tile = [&](int buf) {
        *(uint4*)&As[buf][arow][akq]      = pack4<true>(pa[0]);
        *(uint4*)&As[buf][arow + 64][akq] = pack4<true>(pa[1]);
        uint4 u0 = pack4<true>(pb[0]), u1 = pack4<true>(pb[1]);
        Bs[buf][bc4 * 4 + 0][bkk] = u0.x;
        Bs[buf][bc4 * 4 + 1][bkk] = u0.y;
        Bs[buf][bc4 * 4 + 2][bkk] = u0.z;
        Bs[buf][bc4 * 4 + 3][bkk] = u0.w;
        Bs[buf][(bc4 + 16) * 4 + 0][bkk] = u1.x;
        Bs[buf][(bc4 + 16) * 4 + 1][bkk] = u1.y;
        Bs[buf][(bc4 + 16) * 4 + 2][bkk] = u1.z;
        Bs[buf][(bc4 + 16) * 4 + 3][bkk] = u1.w;
    };

    const int ntiles = K / 16;
    ldg_tile(0);
    sts_tile(0);
    if (ntiles > 1) ldg_tile(16);
    __syncthreads();

    for (int kt = 0; kt < ntiles; kt++) {
        const int buf = kt & 1;
        if (kt + 1 < ntiles) {
            sts_tile(buf ^ 1);
            if (kt + 2 < ntiles) ldg_tile((kt + 2) * 16);
        }

        const uint32_t aoff = buf ? BUFB : 0;
#pragma unroll
        for (int ks = 0; ks < 2; ks++) {
            uint32_t af[2][4], bf[4][4];
            ldsm4(af[0], a_addr0 + aoff + ((ks * 8) << 2));
            ldsm4(af[1], a_addr0 + aoff + ((16 * 20 + ks * 8) << 2));
#pragma unroll
            for (int nj = 0; nj < 4; nj++)
                ldsm4(bf[nj], b_addr0 + aoff + ((nj * 16 * 20 + ks * 8) << 2));
#pragma unroll
            for (int mi = 0; mi < 2; mi++)
#pragma unroll
                for (int ni = 0; ni < 8; ni++)
                    mma8(acc[mi][ni], af[mi], &bf[ni >> 1][(ni & 1) * 2]);
        }
        __syncthreads();
    }

#pragma unroll
    for (int mi = 0; mi < 2; mi++)
#pragma unroll
        for (int ni = 0; ni < 8; ni++) {
            int row = m0 + wm * 32 + mi * 16 + r;
            int col = n0 + wn * 64 + ni * 8 + 2 * c;
            *(float2*)&C[(size_t)row * N + col] =
                make_float2(__uint_as_float(f2tf(acc[mi][ni][0])),
                            __uint_as_float(f2tf(acc[mi][ni][1])));
            *(float2*)&C[(size_t)(row + 8) * N + col] =
                make_float2(__uint_as_float(f2tf(acc[mi][ni][2])),
                            __uint_as_float(f2tf(acc[mi][ni][3])));
        }
}

// ---------------------------------------------------------------------------
// Large NT GEMM, fully cp.async: C = A[M,K] @ B[N,K]^T, both operands
// PRE-ROUNDED tf32. 4-stage smem ring, 1 sync per k-tile.
// Dynamic smem = 4 stages x (A 128x20 + B 128x20) x 4B = 81,920 B.
// CVTC: round C to tf32 on store.
// ---------------------------------------------------------------------------
#define G_STG_W 5120                       // words per stage (A+B)
#define G_BOFF_W 2560                      // B offset within stage (words)
#define GEMM_SMEM_BYTES (4 * G_STG_W * 4)

template<bool CVTC>
__global__ __launch_bounds__(256) void gemm_tb_async(GemmBatch gb, int M, int N, int K)
{
    extern __shared__ uint32_t sm[];
    const float* __restrict__ A  = gb.A[blockIdx.z];
    const float* __restrict__ Bm = gb.B[blockIdx.z];
    float* __restrict__ C        = gb.C[blockIdx.z];

    const int tid  = threadIdx.x;
    const int lane = tid & 31, wid = tid >> 5;
    const int wm = wid & 3, wn = wid >> 2;
    const int m0 = blockIdx.y * 128, n0 = blockIdx.x * 128;
    const int r = lane >> 2, c = lane & 3;

    const int l15   = lane & 15;
    const int khalf = (lane >> 4) & 1;
    const int b_r   = (lane & 7) + ((lane & 16) >> 1);
    const int b_k4  = (lane & 8) >> 1;

    const uint32_t base = smem_u32(sm);
    const uint32_t STGB = G_STG_W * 4;
    const uint32_t a_addr0 = base + (((wm * 32 + l15) * 20 + 4 * khalf) << 2);
    const uint32_t b_addr0 = base + G_BOFF_W * 4 + (((wn * 64 + b_r) * 20 + b_k4) << 2);

    // cp.async coords: 2 threads per row; each thread covers 8 k (2 chunks)
    const int crow = tid >> 1;
    const int ccol = (tid & 1) * 8;        // word col 0 or 8
    const uint32_t sa = base + ((crow * 20 + ccol) << 2);
    const uint32_t sb = base + G_BOFF_W * 4 + ((crow * 20 + ccol) << 2);
    const float* ga  = &A [(size_t)(m0 + crow) * K + ccol];
    const float* gb_ = &Bm[(size_t)(n0 + crow) * K + ccol];

    auto issue = [&](int kt) {
        const uint32_t so = (uint32_t)(kt & 3) * STGB;
        const int k0 = kt * 16;
        cp_async16(sa + so,      ga + k0);
        cp_async16(sa + so + 16, ga + k0 + 4);
        cp_async16(sb + so,      gb_ + k0);
        cp_async16(sb + so + 16, gb_ + k0 + 4);
        cp_commit();
    };

    float acc[2][8][4] = {};
    const int ntiles = K / 16;
    issue(0); issue(1); issue(2);

    for (int kt = 0; kt < ntiles; kt++) {
        asm volatile("cp.async.wait_group 2;" ::: "memory");
        __syncthreads();
        if (kt + 3 < ntiles) issue(kt + 3);
        else cp_commit();                       // keep group count uniform

        const uint32_t so = (uint32_t)(kt & 3) * STGB;
#pragma unroll
        for (int ks = 0; ks < 2; ks++) {
            uint32_t af[2][4], bf[4][4];
            ldsm4(af[0], a_addr0 + so + ((ks * 8) << 2));
            ldsm4(af[1], a_addr0 + so + ((16 * 20 + ks * 8) << 2));
#pragma unroll
            for (int nj = 0; nj < 4; nj++)
                ldsm4(bf[nj], b_addr0 + so + ((nj * 16 * 20 + ks * 8) << 2));
#pragma unroll
            for (int mi = 0; mi < 2; mi++)
#pragma unroll
                for (int ni = 0; ni < 8; ni++)
                    mma8(acc[mi][ni], af[mi], &bf[ni >> 1][(ni & 1) * 2]);
        }
    }

#pragma unroll
    for (int mi = 0; mi < 2; mi++)
#pragma unroll
        for (int ni = 0; ni < 8; ni++) {
            int row = m0 + wm * 32 + mi * 16 + r;
            int col = n0 + wn * 64 + ni * 8 + 2 * c;
            float v0 = acc[mi][ni][0], v1 = acc[mi][ni][1];
            float v2 = acc[mi][ni][2], v3 = acc[mi][ni][3];
            if (CVTC) {
                v0 = __uint_as_float(f2tf(v0)); v1 = __uint_as_float(f2tf(v1));
                v2 = __uint_as_float(f2tf(v2)); v3 = __uint_as_float(f2tf(v3));
            }
            *(float2*)&C[(size_t)row * N + col]       = make_float2(v0, v1);
            *(float2*)&C[(size_t)(row + 8) * N + col] = make_float2(v2, v3);
        }
}

// ---------------------------------------------------------------------------
// Tensor-core flash attention (tf32), 4 warps, 32 q-rows/warp, key tiles 32.
// 3-stage cp.async K/V ring, ONE __syncthreads per tile.
// Dynamic smem layout (uint32 words):
//   stage s: Ks @ s*4480 (32x68), Vs @ s*4480+2176 (32x72)   s=0..2
//   Ps @ 13440: [4][32][36]
// total = (13440 + 4608)*4 = 72,192 B
// ---------------------------------------------------------------------------
#define F_STG_W 4480
#define F_V_W   2176
#define F_PS_W  (3 * F_STG_W)
#define FLASH_SMEM_BYTES ((F_PS_W + 4*32*36) * 4)

__global__ __launch_bounds__(128, 2) void flash_tc()
{
    extern __shared__ uint32_t dsm[];
    uint32_t* Ps = dsm + F_PS_W;

    const int tid  = threadIdx.x;
    const int lane = tid & 31, w = tid >> 5;
    const int r = lane >> 2, c = lane & 3;
    const int s0 = blockIdx.x * 128;
    const int bh = blockIdx.y;
    const int h = bh & (HH - 1), b = bh / HH;

    const int l15   = lane & 15;
    const int khalf = (lane >> 4) & 1;
    const int b_r   = (lane & 7) + ((lane & 16) >> 1);
    const int b_k4  = (lane & 8) >> 1;

    const uint32_t base = smem_u32(dsm);
    const uint32_t ks_addr = base + ((b_r * 68 + b_k4) << 2);
    const uint32_t ps_addr = smem_u32(Ps + w * 32 * 36) + ((l15 * 36 + 4 * khalf) << 2);

    // Q fragments, pre-scaled by 0.125 (exact on tf32 values)
    uint32_t qa[2][8][4];
#pragma unroll
    for (int mi = 0; mi < 2; mi++) {
        const size_t qb = (size_t)(b * SS + s0 + w * 32 + mi * 16) * DD + h * EHD;
#pragma unroll
        for (int kt = 0; kt < 8; kt++) {
            qa[mi][kt][0] = __float_as_uint(0.125f * g_q[qb + (size_t)r       * DD + kt * 8 + c]);
            qa[mi][kt][1] = __float_as_uint(0.125f * g_q[qb + (size_t)(r + 8) * DD + kt * 8 + c]);
            qa[mi][kt][2] = __float_as_uint(0.125f * g_q[qb + (size_t)r       * DD + kt * 8 + c + 4]);
            qa[mi][kt][3] = __float_as_uint(0.125f * g_q[qb + (size_t)(r + 8) * DD + kt * 8 + c + 4]);
        }
    }

    // cp.async loader: 128 threads x 4 rows = full 32-row coverage
    const int trow = tid >> 4;            // 0..7
    const int tc4  = (tid & 15) * 4;
    auto cp_kv = [&](int t0, int st) {
        const uint32_t kdst = base + ((st * F_STG_W) << 2);
        const uint32_t vdst = base + ((st * F_STG_W + F_V_W) << 2);
#pragma unroll
        for (int i = 0; i < 4; i++) {
            const int row = trow + i * 8;
            const size_t g = (size_t)(b * SS + t0 + row) * DD + h * EHD + tc4;
            cp_async16(kdst + ((row * 68 + tc4) << 2), &g_k[g]);
            cp_async16(vdst + ((row * 72 + tc4) << 2), &g_v[g]);
        }
        cp_commit();
    };

    float o[2][8][4] = {};
    float mv[2][2], lv[2][2];
#pragma unroll
    for (int mi = 0; mi < 2; mi++) { mv[mi][0] = mv[mi][1] = -1e30f; lv[mi][0] = lv[mi][1] = 0.f; }

    const int NT = SS / 32;
    cp_kv(0, 0);
    cp_kv(32, 1);

    for (int ti = 0; ti < NT; ti++) {
        const int st = ti % 3;
        asm volatile("cp.async.wait_group 1;" ::: "memory");
        __syncthreads();
        if (ti + 2 < NT) cp_kv((ti + 2) * 32, (ti + 2) % 3);
        else cp_commit();

        const uint32_t koff = (uint32_t)(st * F_STG_W) << 2;

        // S = Q K^T : 32x32 per warp; K B-frags via LDSM
        float sc[2][4][4] = {};
#pragma unroll
        for (int kst = 0; kst < 8; kst++) {
            uint32_t kb[2][4];
            ldsm4(kb[0], ks_addr + koff + ((kst * 8) << 2));
            ldsm4(kb[1], ks_addr + koff + ((16 * 68 + kst * 8) << 2));
#pragma unroll
            for (int nt = 0; nt < 4; nt++) {
                mma8(sc[0][nt], qa[0][kst], &kb[nt >> 1][(nt & 1) * 2]);
                mma8(sc[1][nt], qa[1][kst], &kb[nt >> 1][(nt & 1) * 2]);
            }
        }

        // online softmax per m-tile
        bool need_rescale = false;
        float cor[2][2];
#pragma unroll
        for (int mi = 0; mi < 2; mi++) {
            float t0m = -1e30f, t1m = -1e30f;
#pragma unroll
            for (int nt = 0; nt < 4; nt++) {
                t0m = fmaxf(t0m, fmaxf(sc[mi][nt][0], sc[mi][nt][1]));
                t1m = fmaxf(t1m, fmaxf(sc[mi][nt][2], sc[mi][nt][3]));
            }
            t0m = fmaxf(t0m, __shfl_xor_sync(0xffffffff, t0m, 1));
            t0m = fmaxf(t0m, __shfl_xor_sync(0xffffffff, t0m, 2));
            t1m = fmaxf(t1m, __shfl_xor_sync(0xffffffff, t1m, 1));
            t1m = fmaxf(t1m, __shfl_xor_sync(0xffffffff, t1m, 2));

            float mn0 = fmaxf(mv[mi][0], t0m), mn1 = fmaxf(mv[mi][1], t1m);
            cor[mi][0] = __expf(mv[mi][0] - mn0);
            cor[mi][1] = __expf(mv[mi][1] - mn1);
            need_rescale |= (mn0 > mv[mi][0]) || (mn1 > mv[mi][1]);
            mv[mi][0] = mn0; mv[mi][1] = mn1;

            uint32_t* Pw = Ps + w * 32 * 36;
            float ps0 = 0.f, ps1 = 0.f;
#pragma unroll
            for (int nt = 0; nt < 4; nt++) {
                float p0 = __expf(sc[mi][nt][0] - mn0);
                float p1 = __expf(sc[mi][nt][1] - mn0);
                float p2 = __expf(sc[mi][nt][2] - mn1);
                float p3 = __expf(sc[mi][nt][3] - mn1);
                ps0 += p0 + p1; ps1 += p2 + p3;
                Pw[(mi * 16 + r    ) * 36 + nt * 8 + 2 * c    ] = f2tf(p0);
                Pw[(mi * 16 + r    ) * 36 + nt * 8 + 2 * c + 1] = f2tf(p1);
                Pw[(mi * 16 + r + 8) * 36 + nt * 8 + 2 * c    ] = f2tf(p2);
                Pw[(mi * 16 + r + 8) * 36 + nt * 8 + 2 * c + 1] = f2tf(p3);
            }
            ps0 += __shfl_xor_sync(0xffffffff, ps0, 1);
            ps0 += __shfl_xor_sync(0xffffffff, ps0, 2);
            ps1 += __shfl_xor_sync(0xffffffff, ps1, 1);
            ps1 += __shfl_xor_sync(0xffffffff, ps1, 2);
            lv[mi][0] = lv[mi][0] * cor[mi][0] + ps0;
            lv[mi][1] = lv[mi][1] * cor[mi][1] + ps1;
        }

        if (__ballot_sync(0xffffffff, need_rescale)) {
#pragma unroll
            for (int mi = 0; mi < 2; mi++)
#pragma unroll
                for (int ne = 0; ne < 8; ne++) {
                    o[mi][ne][0] *= cor[mi][0]; o[mi][ne][1] *= cor[mi][0];
                    o[mi][ne][2] *= cor[mi][1]; o[mi][ne][3] *= cor[mi][1];
                }
        }

        __syncwarp();

        // O += P V : P A-frags via LDSM, V B-frags via scalar LDS (conflict-free)
        const uint32_t* Vb = dsm + st * F_STG_W + F_V_W;
#pragma unroll
        for (int k2 = 0; k2 < 4; k2++) {
            uint32_t pa0[4], pa1[4];
            ldsm4(pa0, ps_addr + ((k2 * 8) << 2));
            ldsm4(pa1, ps_addr + ((16 * 36 + k2 * 8) << 2));
#pragma unroll
            for (int ne = 0; ne < 8; ne++) {
                uint32_t bf2[2];
                bf2[0] = Vb[(k2 * 8 + c    ) * 72 + ne * 8 + r];
                bf2[1] = Vb[(k2 * 8 + c + 4) * 72 + ne * 8 + r];
                mma8(o[0][ne], pa0, bf2);
                mma8(o[1][ne], pa1, bf2);
            }
        }
        // no trailing barrier: next iteration's top sync protects buffer reuse
    }

#pragma unroll
    for (int mi = 0; mi < 2; mi++) {
        const float inv0 = 1.f / lv[mi][0], inv1 = 1.f / lv[mi][1];
        const size_t ob = (size_t)(b * SS + s0 + w * 32 + mi * 16) * DD + h * EHD;
#pragma unroll
        for (int ne = 0; ne < 8; ne++) {
            *(float2*)&g_o[ob + (size_t)r * DD + ne * 8 + 2 * c] =
                make_float2(__uint_as_float(f2tf(o[mi][ne][0] * inv0)),
                            __uint_as_float(f2tf(o[mi][ne][1] * inv0)));
            *(float2*)&g_o[ob + (size_t)(r + 8) * DD + ne * 8 + 2 * c] =
                make_float2(__uint_as_float(f2tf(o[mi][ne][2] * inv1)),
                            __uint_as_float(f2tf(o[mi][ne][3] * inv1)));
        }
    }
}

// ---------------------------------------------------------------------------
extern "C" void kernel_launch(void* const* d_in, const int* in_sizes, int n_in,
                              void* d_out, int out_size)
{
    (void)in_sizes; (void)n_in; (void)out_size;
    const float* E  = (const float*)d_in[0];
    const float* WQ = (const float*)d_in[1];
    const float* WK = (const float*)d_in[2];
    const float* WV = (const float*)d_in[3];
    const float* WO = (const float*)d_in[4];
    const float* HQ = (const float*)d_in[5];
    const float* HK = (const float*)d_in[6];
    const float* HV = (const float*)d_in[7];
    float* out = (float*)d_out;

    float *wq, *wk, *wv, *e, *wo, *q, *k, *v, *o;
    cudaGetSymbolAddress((void**)&wq, g_wq);
    cudaGetSymbolAddress((void**)&wk, g_wk);
    cudaGetSymbolAddress((void**)&wv, g_wv);
    cudaGetSymbolAddress((void**)&e,  g_e);
    cudaGetSymbolAddress((void**)&wo, g_wo);
    cudaGetSymbolAddress((void**)&q,  g_q);
    cudaGetSymbolAddress((void**)&k,  g_k);
    cudaGetSymbolAddress((void**)&v,  g_v);
    cudaGetSymbolAddress((void**)&o,  g_o);

    cudaFuncSetAttribute(flash_tc, cudaFuncAttributeMaxDynamicSharedMemorySize,
                         FLASH_SMEM_BYTES);
    cudaFuncSetAttribute(gemm_tb_async<true>,
                         cudaFuncAttributeMaxDynamicSharedMemorySize, GEMM_SMEM_BYTES);
    cudaFuncSetAttribute(gemm_tb_async<false>,
                         cudaFuncAttributeMaxDynamicSharedMemorySize, GEMM_SMEM_BYTES);

    dim3 blk(256);

    // 0) pre-round E and WO to tf32
    round_tf32<<<(MM*DD/4 + 255)/256, 256>>>(E,  e,  MM*DD/4);
    round_tf32<<<(DD*DD/4 + 255)/256, 256>>>(WO, wo, DD*DD/4);

    // 1) Weff = HXcat @ WX (NN), register path, C tf32-rounded
    GemmBatch gw;
    gw.A[0] = HQ; gw.B[0] = WQ; gw.C[0] = wq;
    gw.A[1] = HK; gw.B[1] = WK; gw.C[1] = wk;
    gw.A[2] = HV; gw.B[2] = WV; gw.C[2] = wv;
    gemm_nn<<<dim3(DD/128, DD/128, 3), blk>>>(gw, DD, DD, DD);

    // 2) q/k/v = E_tf32 @ Weff^T (NT, cp.async), C tf32-rounded
    GemmBatch ga;
    ga.A[0] = e; ga.B[0] = wq; ga.C[0] = q;
    ga.A[1] = e; ga.B[1] = wk; ga.C[1] = k;
    ga.A[2] = e; ga.B[2] = wv; ga.C[2] = v;
    gemm_tb_async<true><<<dim3(DD/128, MM/128, 3), blk, GEMM_SMEM_BYTES>>>(ga, MM, DD, DD);

    // 3) attention (writes tf32-rounded o)
    flash_tc<<<dim3(SS/128, BB*HH), 128, FLASH_SMEM_BYTES>>>();

    // 4) out = o @ WO_tf32^T (NT, cp.async), C full fp32
    GemmBatch go;
    go.A[0] = o; go.B[0] = wo; go.C[0] = out;
    go.A[1] = o; go.B[1] = wo; go.C[1] = out;
    go.A[2] = o; go.B[2] = wo; go.C[2] = out;
    gemm_tb_async<false><<<dim3(DD/128, MM/128, 1), blk, GEMM_SMEM_BYTES>>>(go, MM, DD, DD);
}

// round 11
// speedup vs baseline: 1.0639x; 1.0639x over previous
#include <cuda_runtime.h>
#include <cstdint>

#define BB 2
#define SS 2048
#define DD 1024
#define HH 16
#define EHD 64
#define MM (BB*SS)   // 4096

__device__ float g_wq[DD*DD];
__device__ float g_wk[DD*DD];
__device__ float g_wv[DD*DD];
__device__ float g_q[MM*DD];
__device__ float g_k[MM*DD];
__device__ float g_v[MM*DD];
__device__ float g_o[MM*DD];

__device__ __forceinline__ uint32_t f2tf(float x) {
    uint32_t u; asm("cvt.rna.tf32.f32 %0, %1;" : "=r"(u) : "f"(x)); return u;
}

template<bool DOCVT>
__device__ __forceinline__ uint4 pack4(float4 v) {
    if (DOCVT)
        return make_uint4(f2tf(v.x), f2tf(v.y), f2tf(v.z), f2tf(v.w));
    return make_uint4(__float_as_uint(v.x), __float_as_uint(v.y),
                      __float_as_uint(v.z), __float_as_uint(v.w));
}

__device__ __forceinline__ uint32_t smem_u32(const void* p) {
    uint32_t a;
    asm("{ .reg .u64 t; cvta.to.shared.u64 t, %1; cvt.u32.u64 %0, t; }"
        : "=r"(a) : "l"(p));
    return a;
}

__device__ __forceinline__ void ldsm4(uint32_t* d, uint32_t addr) {
    asm volatile("ldmatrix.sync.aligned.m8n8.x4.shared.b16 {%0,%1,%2,%3}, [%4];"
        : "=r"(d[0]), "=r"(d[1]), "=r"(d[2]), "=r"(d[3]) : "r"(addr));
}

__device__ __forceinline__ void mma8(float* d, const uint32_t* a, const uint32_t* b) {
    asm volatile("mma.sync.aligned.m16n8k8.row.col.f32.tf32.tf32.f32 "
        "{%0,%1,%2,%3}, {%4,%5,%6,%7}, {%8,%9}, {%0,%1,%2,%3};\n"
        : "+f"(d[0]), "+f"(d[1]), "+f"(d[2]), "+f"(d[3])
        : "r"(a[0]), "r"(a[1]), "r"(a[2]), "r"(a[3]), "r"(b[0]), "r"(b[1]));
}

__device__ __forceinline__ void cp_async16(uint32_t saddr, const void* gaddr) {
    asm volatile("cp.async.ca.shared.global [%0], [%1], 16;"
                 :: "r"(saddr), "l"(gaddr) : "memory");
}
__device__ __forceinline__ void cp_commit() {
    asm volatile("cp.async.commit_group;" ::: "memory");
}

__device__ __forceinline__ float ex2(float x) {
    float r; asm("ex2.approx.f32 %0, %1;" : "=f"(r) : "f"(x)); return r;
}

struct GemmBatch {
    const float* A[3];
    const float* B[3];
    float*       C[3];
};

// ---------------------------------------------------------------------------
// TF32 tensor-core GEMM (R8-proven), z-batched, 2-stage smem double-buffer,
// LDSM fragments. Static smem = 40 KB.
//  TB=true : C = A[M,K] @ B[N,K]^T ;  TB=false: C = A[M,K] @ B[K,N]
//  CVTA/CVTB: tf32-round on load path (false if operand pre-rounded)
//  CVTC: tf32-round C on store
// ---------------------------------------------------------------------------
template<bool TB, bool CVTA, bool CVTB, bool CVTC>
__global__ __launch_bounds__(256) void gemm_tc(GemmBatch gb, int M, int N, int K)
{
    __shared__ uint32_t As[2][128][20];
    __shared__ uint32_t Bs[2][128][20];
    const float* __restrict__ A  = gb.A[blockIdx.z];
    const float* __restrict__ Bm = gb.B[blockIdx.z];
    float* __restrict__ C        = gb.C[blockIdx.z];

    const int tid  = threadIdx.x;
    const int lane = tid & 31, wid = tid >> 5;
    const int wm = wid & 3, wn = wid >> 2;
    const int m0 = blockIdx.y * 128, n0 = blockIdx.x * 128;
    const int r = lane >> 2, c = lane & 3;

    const int l15   = lane & 15;
    const int khalf = (lane >> 4) & 1;
    const int b_r   = (lane & 7) + ((lane & 16) >> 1);
    const int b_k4  = (lane & 8) >> 1;

    const uint32_t As_base = smem_u32(&As[0][0][0]);
    const uint32_t Bs_base = smem_u32(&Bs[0][0][0]);
    const uint32_t BUFB = 128 * 20 * 4;
    const uint32_t a_addr0 = As_base + (((wm * 32 + l15) * 20 + 4 * khalf) << 2);
    const uint32_t b_addr0 = Bs_base + (((wn * 64 + b_r) * 20 + b_k4) << 2);

    const int arow = tid >> 2, akq = (tid & 3) * 4;      // A / B(TB): rows arow, arow+64
    const int bkk  = tid & 15, bc4 = tid >> 4;           // B(NN)

    float acc[2][8][4] = {};
    float4 pa[2], pb[2];

    auto ldg_tile = [&](int k0) {
        pa[0] = *(const float4*)&A[(size_t)(m0 + arow) * K + k0 + akq];
        pa[1] = *(const float4*)&A[(size_t)(m0 + arow + 64) * K + k0 + akq];
        if (TB) {
            pb[0] = *(const float4*)&Bm[(size_t)(n0 + arow) * K + k0 + akq];
            pb[1] = *(const float4*)&Bm[(size_t)(n0 + arow + 64) * K + k0 + akq];
        } else {
            pb[0] = *(const float4*)&Bm[(size_t)(k0 + bkk) * N + n0 + bc4 * 4];
            pb[1] = *(const float4*)&Bm[(size_t)(k0 + bkk) * N + n0 + (bc4 + 16) * 4];
        }
    };
    auto sts_tile = [&](int buf) {
        *(uint4*)&As[buf][arow][akq]      = pack4<CVTA>(pa[0]);
        *(uint4*)&As[buf][arow + 64][akq] = pack4<CVTA>(pa[1]);
        if (TB) {
            *(uint4*)&Bs[buf][arow][akq]      = pack4<CVTB>(pb[0]);
            *(uint4*)&Bs[buf][arow + 64][akq] = pack4<CVTB>(pb[1]);
        } else {
            uint4 u0 = pack4<CVTB>(pb[0]), u1 = pack4<CVTB>(pb[1]);
            Bs[buf][bc4 * 4 + 0][bkk] = u0.x;
            Bs[buf][bc4 * 4 + 1][bkk] = u0.y;
            Bs[buf][bc4 * 4 + 2][bkk] = u0.z;
            Bs[buf][bc4 * 4 + 3][bkk] = u0.w;
            Bs[buf][(bc4 + 16) * 4 + 0][bkk] = u1.x;
            Bs[buf][(bc4 + 16) * 4 + 1][bkk] = u1.y;
            Bs[buf][(bc4 + 16) * 4 + 2][bkk] = u1.z;
            Bs[buf][(bc4 + 16) * 4 + 3][bkk] = u1.w;
        }
    };

    const int ntiles = K / 16;
    ldg_tile(0);
    sts_tile(0);
    if (ntiles > 1) ldg_tile(16);
    __syncthreads();

    for (int kt = 0; kt < ntiles; kt++) {
        const int buf = kt & 1;
        if (kt + 1 < ntiles) {
            sts_tile(buf ^ 1);
            if (kt + 2 < ntiles) ldg_tile((kt + 2) * 16);
        }

        const uint32_t aoff = buf ? BUFB : 0;
#pragma unroll
        for (int ks = 0; ks < 2; ks++) {
            uint32_t af[2][4], bf[4][4];
            ldsm4(af[0], a_addr0 + aoff + ((ks * 8) << 2));
            ldsm4(af[1], a_addr0 + aoff + ((16 * 20 + ks * 8) << 2));
#pragma unroll
            for (int nj = 0; nj < 4; nj++)
                ldsm4(bf[nj], b_addr0 + aoff + ((nj * 16 * 20 + ks * 8) << 2));
#pragma unroll
            for (int mi = 0; mi < 2; mi++)
#pragma unroll
                for (int ni = 0; ni < 8; ni++)
                    mma8(acc[mi][ni], af[mi], &bf[ni >> 1][(ni & 1) * 2]);
        }
        __syncthreads();
    }

#pragma unroll
    for (int mi = 0; mi < 2; mi++)
#pragma unroll
        for (int ni = 0; ni < 8; ni++) {
            int row = m0 + wm * 32 + mi * 16 + r;
            int col = n0 + wn * 64 + ni * 8 + 2 * c;
            float v0 = acc[mi][ni][0], v1 = acc[mi][ni][1];
            float v2 = acc[mi][ni][2], v3 = acc[mi][ni][3];
            if (CVTC) {
                v0 = __uint_as_float(f2tf(v0)); v1 = __uint_as_float(f2tf(v1));
                v2 = __uint_as_float(f2tf(v2)); v3 = __uint_as_float(f2tf(v3));
            }
            *(float2*)&C[(size_t)row * N + col]       = make_float2(v0, v1);
            *(float2*)&C[(size_t)(row + 8) * N + col] = make_float2(v2, v3);
        }
}

// ---------------------------------------------------------------------------
// Flash attention (tf32 mma.sync), KEY TILE = 64 (halved per-key serial cost:
// barriers, shfl reductions, rescale checks). 2-buffer cp.async K/V.
// exp2-domain softmax: Q pre-scaled by 0.125*log2(e), p = ex2(s - m).
// smem words: Ks [2][64][68] @0, Vs [2][64][72] @8704, Ps [4][32][68] @17920
// total = 26624 words = 106,496 B  (occ 2: 213 KB/SM)
// ---------------------------------------------------------------------------
#define KS_OFF 0
#define VS_OFF (2*64*68)
#define PS_OFF (VS_OFF + 2*64*72)
#define FLASH_SMEM_BYTES ((PS_OFF + 4*32*68) * 4)

__global__ __launch_bounds__(128, 2) void flash_tc()
{
    extern __shared__ uint32_t dsm[];
    uint32_t* Ks = dsm + KS_OFF;
    uint32_t* Vs = dsm + VS_OFF;
    uint32_t* Ps = dsm + PS_OFF;

    const int tid  = threadIdx.x;
    const int lane = tid & 31, w = tid >> 5;
    const int r = lane >> 2, c = lane & 3;
    const int s0 = blockIdx.x * 128;
    const int bh = blockIdx.y;
    const int h = bh & (HH - 1), b = bh / HH;

    const int l15   = lane & 15;
    const int khalf = (lane >> 4) & 1;
    const int b_r   = (lane & 7) + ((lane & 16) >> 1);
    const int b_k4  = (lane & 8) >> 1;

    const uint32_t KBUF = 64 * 68 * 4;
    const uint32_t ks_base = smem_u32(Ks);
    const uint32_t vs_base = smem_u32(Vs);
    const uint32_t ks_addr = ks_base + ((b_r * 68 + b_k4) << 2);
    const uint32_t ps_addr = smem_u32(Ps + w * 32 * 68) + ((l15 * 68 + 4 * khalf) << 2);

    // Q fragments, pre-scaled by 0.125 * log2(e) (exp2-domain softmax)
    const float QS = 0.18033688f;
    uint32_t qa[2][8][4];
#pragma unroll
    for (int mi = 0; mi < 2; mi++) {
        const size_t qb = (size_t)(b * SS + s0 + w * 32 + mi * 16) * DD + h * EHD;
#pragma unroll
        for (int kt = 0; kt < 8; kt++) {
            qa[mi][kt][0] = f2tf(QS * g_q[qb + (size_t)r       * DD + kt * 8 + c]);
            qa[mi][kt][1] = f2tf(QS * g_q[qb + (size_t)(r + 8) * DD + kt * 8 + c]);
            qa[mi][kt][2] = f2tf(QS * g_q[qb + (size_t)r       * DD + kt * 8 + c + 4]);
            qa[mi][kt][3] = f2tf(QS * g_q[qb + (size_t)(r + 8) * DD + kt * 8 + c + 4]);
        }
    }

    // cp.async loader: 128 threads x 8 rows each = full 64-row coverage
    const int trow = tid >> 4;            // 0..7
    const int tc4  = (tid & 15) * 4;
    auto cp_kv = [&](int t0, int buf) {
#pragma unroll
        for (int i = 0; i < 8; i++) {
            const int row = trow + i * 8;                 // 0..63 full coverage
            const size_t g = (size_t)(b * SS + t0 + row) * DD + h * EHD + tc4;
            cp_async16(ks_base + ((buf * 64 * 68 + row * 68 + tc4) << 2), &g_k[g]);
            cp_async16(vs_base + ((buf * 64 * 72 + row * 72 + tc4) << 2), &g_v[g]);
        }
        cp_commit();
    };

    float o[2][8][4] = {};
    float mv[2][2], lv[2][2];
#pragma unroll
    for (int mi = 0; mi < 2; mi++) { mv[mi][0] = mv[mi][1] = -1e30f; lv[mi][0] = lv[mi][1] = 0.f; }

    const int NT = SS / 64;               // 32 tiles
    cp_kv(0, 0);
    cp_kv(64, 1);

    for (int ti = 0; ti < NT; ti++) {
        const int buf = ti & 1;
        asm volatile("cp.async.wait_group 1;" ::: "memory");
        __syncthreads();

        const uint32_t koff = buf ? KBUF : 0;

        // S = Q K^T : 32x64 per warp (2 m-tiles x 8 n-tiles)
        float sc[2][8][4] = {};
#pragma unroll
        for (int kst = 0; kst < 8; kst++) {
            uint32_t kb[4][4];
#pragma unroll
            for (int j = 0; j < 4; j++)
                ldsm4(kb[j], ks_addr + koff + ((j * 16 * 68 + kst * 8) << 2));
#pragma unroll
            for (int nt = 0; nt < 8; nt++) {
                mma8(sc[0][nt], qa[0][kst], &kb[nt >> 1][(nt & 1) * 2]);
                mma8(sc[1][nt], qa[1][kst], &kb[nt >> 1][(nt & 1) * 2]);
            }
        }

        // online softmax (log2 domain) per m-tile
        bool need_rescale = false;
        float cor[2][2];
#pragma unroll
        for (int mi = 0; mi < 2; mi++) {
            float t0m = -1e30f, t1m = -1e30f;
#pragma unroll
            for (int nt = 0; nt < 8; nt++) {
                t0m = fmaxf(t0m, fmaxf(sc[mi][nt][0], sc[mi][nt][1]));
                t1m = fmaxf(t1m, fmaxf(sc[mi][nt][2], sc[mi][nt][3]));
            }
            t0m = fmaxf(t0m, __shfl_xor_sync(0xffffffff, t0m, 1));
            t0m = fmaxf(t0m, __shfl_xor_sync(0xffffffff, t0m, 2));
            t1m = fmaxf(t1m, __shfl_xor_sync(0xffffffff, t1m, 1));
            t1m = fmaxf(t1m, __shfl_xor_sync(0xffffffff, t1m, 2));

            float mn0 = fmaxf(mv[mi][0], t0m), mn1 = fmaxf(mv[mi][1], t1m);
            cor[mi][0] = ex2(mv[mi][0] - mn0);
            cor[mi][1] = ex2(mv[mi][1] - mn1);
            need_rescale |= (mn0 > mv[mi][0]) || (mn1 > mv[mi][1]);
            mv[mi][0] = mn0; mv[mi][1] = mn1;

            uint32_t* Pw = Ps + w * 32 * 68;
            float ps0 = 0.f, ps1 = 0.f;
#pragma unroll
            for (int nt = 0; nt < 8; nt++) {
                float p0 = ex2(sc[mi][nt][0] - mn0);
                float p1 = ex2(sc[mi][nt][1] - mn0);
                float p2 = ex2(sc[mi][nt][2] - mn1);
                float p3 = ex2(sc[mi][nt][3] - mn1);
                ps0 += p0 + p1; ps1 += p2 + p3;
                Pw[(mi * 16 + r    ) * 68 + nt * 8 + 2 * c    ] = f2tf(p0);
                Pw[(mi * 16 + r    ) * 68 + nt * 8 + 2 * c + 1] = f2tf(p1);
                Pw[(mi * 16 + r + 8) * 68 + nt * 8 + 2 * c    ] = f2tf(p2);
                Pw[(mi * 16 + r + 8) * 68 + nt * 8 + 2 * c + 1] = f2tf(p3);
            }
            ps0 += __shfl_xor_sync(0xffffffff, ps0, 1);
            ps0 += __shfl_xor_sync(0xffffffff, ps0, 2);
            ps1 += __shfl_xor_sync(0xffffffff, ps1, 1);
            ps1 += __shfl_xor_sync(0xffffffff, ps1, 2);
            lv[mi][0] = lv[mi][0] * cor[mi][0] + ps0;
            lv[mi][1] = lv[mi][1] * cor[mi][1] + ps1;
        }

        if (__ballot_sync(0xffffffff, need_rescale)) {
#pragma unroll
            for (int mi = 0; mi < 2; mi++)
#pragma unroll
                for (int ne = 0; ne < 8; ne++) {
                    o[mi][ne][0] *= cor[mi][0]; o[mi][ne][1] *= cor[mi][0];
                    o[mi][ne][2] *= cor[mi][1]; o[mi][ne][3] *= cor[mi][1];
                }
        }

        __syncwarp();

        // O += P V : P A-frags via LDSM, V B-frags via scalar LDS
        const uint32_t* Vb = Vs + (size_t)buf * 64 * 72;
#pragma unroll
        for (int k2 = 0; k2 < 8; k2++) {
            uint32_t pa0[4], pa1[4];
            ldsm4(pa0, ps_addr + ((k2 * 8) << 2));
            ldsm4(pa1, ps_addr + ((16 * 68 + k2 * 8) << 2));
#pragma unroll
            for (int ne = 0; ne < 8; ne++) {
                uint32_t bf2[2];
                bf2[0] = Vb[(k2 * 8 + c    ) * 72 + ne * 8 + r];
                bf2[1] = Vb[(k2 * 8 + c + 4) * 72 + ne * 8 + r];
                mma8(o[0][ne], pa0, bf2);
                mma8(o[1][ne], pa1, bf2);
            }
        }

        __syncthreads();
        if (ti + 2 < NT) cp_kv((ti + 2) * 64, buf);
    }

#pragma unroll
    for (int mi = 0; mi < 2; mi++) {
        const float inv0 = 1.f / lv[mi][0], inv1 = 1.f / lv[mi][1];
        const size_t ob = (size_t)(b * SS + s0 + w * 32 + mi * 16) * DD + h * EHD;
#pragma unroll
        for (int ne = 0; ne < 8; ne++) {
            *(float2*)&g_o[ob + (size_t)r * DD + ne * 8 + 2 * c] =
                make_float2(__uint_as_float(f2tf(o[mi][ne][0] * inv0)),
                            __uint_as_float(f2tf(o[mi][ne][1] * inv0)));
            *(float2*)&g_o[ob + (size_t)(r + 8) * DD + ne * 8 + 2 * c] =
                make_float2(__uint_as_float(f2tf(o[mi][ne][2] * inv1)),
                            __uint_as_float(f2tf(o[mi][ne][3] * inv1)));
        }
    }
}

// ---------------------------------------------------------------------------
extern "C" void kernel_launch(void* const* d_in, const int* in_sizes, int n_in,
                              void* d_out, int out_size)
{
    (void)in_sizes; (void)n_in; (void)out_size;
    const float* E  = (const float*)d_in[0];
    const float* WQ = (const float*)d_in[1];
    const float* WK = (const float*)d_in[2];
    const float* WV = (const float*)d_in[3];
    const float* WO = (const float*)d_in[4];
    const float* HQ = (const float*)d_in[5];
    const float* HK = (const float*)d_in[6];
    const float* HV = (const float*)d_in[7];
    float* out = (float*)d_out;

    float *wq, *wk, *wv, *q, *k, *v, *o;
    cudaGetSymbolAddress((void**)&wq, g_wq);
    cudaGetSymbolAddress((void**)&wk, g_wk);
    cudaGetSymbolAddress((void**)&wv, g_wv);
    cudaGetSymbolAddress((void**)&q,  g_q);
    cudaGetSymbolAddress((void**)&k,  g_k);
    cudaGetSymbolAddress((void**)&v,  g_v);
    cudaGetSymbolAddress((void**)&o,  g_o);

    cudaFuncSetAttribute(flash_tc, cudaFuncAttributeMaxDynamicSharedMemorySize,
                         FLASH_SMEM_BYTES);

    dim3 blk(256);

    // 1) Weff = HXcat @ WX (NN). A,B external -> cvt; C pre-rounded.
    GemmBatch gw;
    gw.A[0] = HQ; gw.B[0] = WQ; gw.C[0] = wq;
    gw.A[1] = HK; gw.B[1] = WK; gw.C[1] = wk;
    gw.A[2] = HV; gw.B[2] = WV; gw.C[2] = wv;
    gemm_tc<false, true, true, true><<<dim3(DD/128, DD/128, 3), blk>>>(gw, DD, DD, DD);

    // 2) q/k/v = E @ Weff^T (NT). A external -> cvt; B pre-rounded; C pre-rounded.
    GemmBatch ga;
    ga.A[0] = E; ga.B[0] = wq; ga.C[0] = q;
    ga.A[1] = E; ga.B[1] = wk; ga.C[1] = k;
    ga.A[2] = E; ga.B[2] = wv; ga.C[2] = v;
    gemm_tc<true, true, false, true><<<dim3(DD/128, MM/128, 3), blk>>>(ga, MM, DD, DD);

    // 3) attention (writes tf32-rounded o)
    flash_tc<<<dim3(SS/128, BB*HH), 128, FLASH_SMEM_BYTES>>>();

    // 4) out = o @ WO^T. A pre-rounded; B external -> cvt; C full fp32.
    GemmBatch go;
    go.A[0] = o; go.B[0] = WO; go.C[0] = out;
    go.A[1] = o; go.B[1] = WO; go.C[1] = out;
    go.A[2] = o; go.B[2] = WO; go.C[2] = out;
    gemm_tc<true, false, true, false><<<dim3(DD/128, MM/128, 1), blk>>>(go, MM, DD, DD);
}

// round 12
// speedup vs baseline: 1.0903x; 1.0248x over previous
#include <cuda_runtime.h>
#include <cstdint>

#define BB 2
#define SS 2048
#define DD 1024
#define HH 16
#define EHD 64
#define MM (BB*SS)   // 4096

__device__ float g_wq[DD*DD];
__device__ float g_wk[DD*DD];
__device__ float g_wv[DD*DD];
__device__ float g_q[MM*DD];
__device__ float g_k[MM*DD];
__device__ float g_v[MM*DD];
__device__ float g_o[MM*DD];

__device__ __forceinline__ uint32_t f2tf(float x) {
    uint32_t u; asm("cvt.rna.tf32.f32 %0, %1;" : "=r"(u) : "f"(x)); return u;
}

template<bool DOCVT>
__device__ __forceinline__ uint4 pack4(float4 v) {
    if (DOCVT)
        return make_uint4(f2tf(v.x), f2tf(v.y), f2tf(v.z), f2tf(v.w));
    return make_uint4(__float_as_uint(v.x), __float_as_uint(v.y),
                      __float_as_uint(v.z), __float_as_uint(v.w));
}

__device__ __forceinline__ uint32_t smem_u32(const void* p) {
    uint32_t a;
    asm("{ .reg .u64 t; cvta.to.shared.u64 t, %1; cvt.u32.u64 %0, t; }"
        : "=r"(a) : "l"(p));
    return a;
}

__device__ __forceinline__ void ldsm4(uint32_t* d, uint32_t addr) {
    asm volatile("ldmatrix.sync.aligned.m8n8.x4.shared.b16 {%0,%1,%2,%3}, [%4];"
        : "=r"(d[0]), "=r"(d[1]), "=r"(d[2]), "=r"(d[3]) : "r"(addr));
}

__device__ __forceinline__ void mma8(float* d, const uint32_t* a, const uint32_t* b) {
    asm volatile("mma.sync.aligned.m16n8k8.row.col.f32.tf32.tf32.f32 "
        "{%0,%1,%2,%3}, {%4,%5,%6,%7}, {%8,%9}, {%0,%1,%2,%3};\n"
        : "+f"(d[0]), "+f"(d[1]), "+f"(d[2]), "+f"(d[3])
        : "r"(a[0]), "r"(a[1]), "r"(a[2]), "r"(a[3]), "r"(b[0]), "r"(b[1]));
}

__device__ __forceinline__ void cp_async16(uint32_t saddr, const void* gaddr) {
    asm volatile("cp.async.ca.shared.global [%0], [%1], 16;"
                 :: "r"(saddr), "l"(gaddr) : "memory");
}
__device__ __forceinline__ void cp_commit() {
    asm volatile("cp.async.commit_group;" ::: "memory");
}

__device__ __forceinline__ float ex2(float x) {
    float r; asm("ex2.approx.f32 %0, %1;" : "=f"(r) : "f"(x)); return r;
}

struct GemmBatch {
    const float* A[3];
    const float* B[3];
    float*       C[3];
};

// ---------------------------------------------------------------------------
// TF32 tensor-core GEMM, 128 threads / 4 warps, warp tile 64x64 (2x2 grid),
// CTA tile 128x128, BK=16, 2-stage smem double-buffer, LDSM fragments.
// Per k-tile smem reads 32KB (vs 48KB at 32x64 warp tile); 4.0 mma/LDSM.
//  TB=true : C = A[M,K] @ B[N,K]^T ;  TB=false: C = A[M,K] @ B[K,N]
//  CVTA/CVTB: tf32-round on load path; CVTC: tf32-round C on store
// ---------------------------------------------------------------------------
template<bool TB, bool CVTA, bool CVTB, bool CVTC>
__global__ __launch_bounds__(128) void gemm_tc(GemmBatch gb, int M, int N, int K)
{
    __shared__ uint32_t As[2][128][20];
    __shared__ uint32_t Bs[2][128][20];
    const float* __restrict__ A  = gb.A[blockIdx.z];
    const float* __restrict__ Bm = gb.B[blockIdx.z];
    float* __restrict__ C        = gb.C[blockIdx.z];

    const int tid  = threadIdx.x;
    const int lane = tid & 31, wid = tid >> 5;
    const int wm = wid & 1, wn = wid >> 1;           // 2x2 warp grid
    const int m0 = blockIdx.y * 128, n0 = blockIdx.x * 128;
    const int r = lane >> 2, c = lane & 3;

    const int l15   = lane & 15;
    const int khalf = (lane >> 4) & 1;
    const int b_r   = (lane & 7) + ((lane & 16) >> 1);
    const int b_k4  = (lane & 8) >> 1;

    const uint32_t As_base = smem_u32(&As[0][0][0]);
    const uint32_t Bs_base = smem_u32(&Bs[0][0][0]);
    const uint32_t BUFB = 128 * 20 * 4;
    const uint32_t a_addr0 = As_base + (((wm * 64 + l15) * 20 + 4 * khalf) << 2);
    const uint32_t b_addr0 = Bs_base + (((wn * 64 + b_r) * 20 + b_k4) << 2);

    // load coords (128 threads): A/B(TB): rows arow+32i; B(NN): cols (bc4+8i)*4
    const int arow = tid >> 2, akq = (tid & 3) * 4;
    const int bkk  = tid & 15, bc4 = tid >> 4;       // bc4 0..7

    float acc[4][8][4] = {};
    float4 pa[4], pb[4];

    auto ldg_tile = [&](int k0) {
#pragma unroll
        for (int i = 0; i < 4; i++)
            pa[i] = *(const float4*)&A[(size_t)(m0 + arow + 32 * i) * K + k0 + akq];
        if (TB) {
#pragma unroll
            for (int i = 0; i < 4; i++)
                pb[i] = *(const float4*)&Bm[(size_t)(n0 + arow + 32 * i) * K + k0 + akq];
        } else {
#pragma unroll
            for (int i = 0; i < 4; i++)
                pb[i] = *(const float4*)&Bm[(size_t)(k0 + bkk) * N + n0 + (bc4 + 8 * i) * 4];
        }
    };
    auto sts_tile = [&](int buf) {
#pragma unroll
        for (int i = 0; i < 4; i++)
            *(uint4*)&As[buf][arow + 32 * i][akq] = pack4<CVTA>(pa[i]);
        if (TB) {
#pragma unroll
            for (int i = 0; i < 4; i++)
                *(uint4*)&Bs[buf][arow + 32 * i][akq] = pack4<CVTB>(pb[i]);
        } else {
#pragma unroll
            for (int i = 0; i < 4; i++) {
                uint4 u = pack4<CVTB>(pb[i]);
                Bs[buf][(bc4 + 8 * i) * 4 + 0][bkk] = u.x;
                Bs[buf][(bc4 + 8 * i) * 4 + 1][bkk] = u.y;
                Bs[buf][(bc4 + 8 * i) * 4 + 2][bkk] = u.z;
                Bs[buf][(bc4 + 8 * i) * 4 + 3][bkk] = u.w;
            }
        }
    };

    const int ntiles = K / 16;
    ldg_tile(0);
    sts_tile(0);
    if (ntiles > 1) ldg_tile(16);
    __syncthreads();

    for (int kt = 0; kt < ntiles; kt++) {
        const int buf = kt & 1;
        if (kt + 1 < ntiles) {
            sts_tile(buf ^ 1);
            if (kt + 2 < ntiles) ldg_tile((kt + 2) * 16);
        }

        const uint32_t aoff = buf ? BUFB : 0;
#pragma unroll
        for (int ks = 0; ks < 2; ks++) {
            uint32_t af[4][4], bf[4][4];
#pragma unroll
            for (int mi = 0; mi < 4; mi++)
                ldsm4(af[mi], a_addr0 + aoff + ((mi * 16 * 20 + ks * 8) << 2));
#pragma unroll
            for (int nj = 0; nj < 4; nj++)
                ldsm4(bf[nj], b_addr0 + aoff + ((nj * 16 * 20 + ks * 8) << 2));
#pragma unroll
            for (int mi = 0; mi < 4; mi++)
#pragma unroll
                for (int ni = 0; ni < 8; ni++)
                    mma8(acc[mi][ni], af[mi], &bf[ni >> 1][(ni & 1) * 2]);
        }
        __syncthreads();
    }

#pragma unroll
    for (int mi = 0; mi < 4; mi++)
#pragma unroll
        for (int ni = 0; ni < 8; ni++) {
            int row = m0 + wm * 64 + mi * 16 + r;
            int col = n0 + wn * 64 + ni * 8 + 2 * c;
            float v0 = acc[mi][ni][0], v1 = acc[mi][ni][1];
            float v2 = acc[mi][ni][2], v3 = acc[mi][ni][3];
            if (CVTC) {
                v0 = __uint_as_float(f2tf(v0)); v1 = __uint_as_float(f2tf(v1));
                v2 = __uint_as_float(f2tf(v2)); v3 = __uint_as_float(f2tf(v3));
            }
            *(float2*)&C[(size_t)row * N + col]       = make_float2(v0, v1);
            *(float2*)&C[(size_t)(row + 8) * N + col] = make_float2(v2, v3);
        }
}

// ---------------------------------------------------------------------------
// Flash attention (tf32 mma.sync), key tile 64, exp2 softmax — R11 verbatim.
// smem words: Ks [2][64][68] @0, Vs [2][64][72] @8704, Ps [4][32][68] @17920
// total 106,496 B (occ 2)
// ---------------------------------------------------------------------------
#define KS_OFF 0
#define VS_OFF (2*64*68)
#define PS_OFF (VS_OFF + 2*64*72)
#define FLASH_SMEM_BYTES ((PS_OFF + 4*32*68) * 4)

__global__ __launch_bounds__(128, 2) void flash_tc()
{
    extern __shared__ uint32_t dsm[];
    uint32_t* Ks = dsm + KS_OFF;
    uint32_t* Vs = dsm + VS_OFF;
    uint32_t* Ps = dsm + PS_OFF;

    const int tid  = threadIdx.x;
    const int lane = tid & 31, w = tid >> 5;
    const int r = lane >> 2, c = lane & 3;
    const int s0 = blockIdx.x * 128;
    const int bh = blockIdx.y;
    const int h = bh & (HH - 1), b = bh / HH;

    const int l15   = lane & 15;
    const int khalf = (lane >> 4) & 1;
    const int b_r   = (lane & 7) + ((lane & 16) >> 1);
    const int b_k4  = (lane & 8) >> 1;

    const uint32_t KBUF = 64 * 68 * 4;
    const uint32_t ks_base = smem_u32(Ks);
    const uint32_t vs_base = smem_u32(Vs);
    const uint32_t ks_addr = ks_base + ((b_r * 68 + b_k4) << 2);
    const uint32_t ps_addr = smem_u32(Ps + w * 32 * 68) + ((l15 * 68 + 4 * khalf) << 2);

    const float QS = 0.18033688f;   // 0.125 * log2(e)
    uint32_t qa[2][8][4];
#pragma unroll
    for (int mi = 0; mi < 2; mi++) {
        const size_t qb = (size_t)(b * SS + s0 + w * 32 + mi * 16) * DD + h * EHD;
#pragma unroll
        for (int kt = 0; kt < 8; kt++) {
            qa[mi][kt][0] = f2tf(QS * g_q[qb + (size_t)r       * DD + kt * 8 + c]);
            qa[mi][kt][1] = f2tf(QS * g_q[qb + (size_t)(r + 8) * DD + kt * 8 + c]);
            qa[mi][kt][2] = f2tf(QS * g_q[qb + (size_t)r       * DD + kt * 8 + c + 4]);
            qa[mi][kt][3] = f2tf(QS * g_q[qb + (size_t)(r + 8) * DD + kt * 8 + c + 4]);
        }
    }

    const int trow = tid >> 4;
    const int tc4  = (tid & 15) * 4;
    auto cp_kv = [&](int t0, int buf) {
#pragma unroll
        for (int i = 0; i < 8; i++) {
            const int row = trow + i * 8;
            const size_t g = (size_t)(b * SS + t0 + row) * DD + h * EHD + tc4;
            cp_async16(ks_base + ((buf * 64 * 68 + row * 68 + tc4) << 2), &g_k[g]);
            cp_async16(vs_base + ((buf * 64 * 72 + row * 72 + tc4) << 2), &g_v[g]);
        }
        cp_commit();
    };

    float o[2][8][4] = {};
    float mv[2][2], lv[2][2];
#pragma unroll
    for (int mi = 0; mi < 2; mi++) { mv[mi][0] = mv[mi][1] = -1e30f; lv[mi][0] = lv[mi][1] = 0.f; }

    const int NT = SS / 64;
    cp_kv(0, 0);
    cp_kv(64, 1);

    for (int ti = 0; ti < NT; ti++) {
        const int buf = ti & 1;
        asm volatile("cp.async.wait_group 1;" ::: "memory");
        __syncthreads();

        const uint32_t koff = buf ? KBUF : 0;

        float sc[2][8][4] = {};
#pragma unroll
        for (int kst = 0; kst < 8; kst++) {
            uint32_t kb[4][4];
#pragma unroll
            for (int j = 0; j < 4; j++)
                ldsm4(kb[j], ks_addr + koff + ((j * 16 * 68 + kst * 8) << 2));
#pragma unroll
            for (int nt = 0; nt < 8; nt++) {
                mma8(sc[0][nt], qa[0][kst], &kb[nt >> 1][(nt & 1) * 2]);
                mma8(sc[1][nt], qa[1][kst], &kb[nt >> 1][(nt & 1) * 2]);
            }
        }

        bool need_rescale = false;
        float cor[2][2];
#pragma unroll
        for (int mi = 0; mi < 2; mi++) {
            float t0m = -1e30f, t1m = -1e30f;
#pragma unroll
            for (int nt = 0; nt < 8; nt++) {
                t0m = fmaxf(t0m, fmaxf(sc[mi][nt][0], sc[mi][nt][1]));
                t1m = fmaxf(t1m, fmaxf(sc[mi][nt][2], sc[mi][nt][3]));
            }
            t0m = fmaxf(t0m, __shfl_xor_sync(0xffffffff, t0m, 1));
            t0m = fmaxf(t0m, __shfl_xor_sync(0xffffffff, t0m, 2));
            t1m = fmaxf(t1m, __shfl_xor_sync(0xffffffff, t1m, 1));
            t1m = fmaxf(t1m, __shfl_xor_sync(0xffffffff, t1m, 2));

            float mn0 = fmaxf(mv[mi][0], t0m), mn1 = fmaxf(mv[mi][1], t1m);
            cor[mi][0] = ex2(mv[mi][0] - mn0);
            cor[mi][1] = ex2(mv[mi][1] - mn1);
            need_rescale |= (mn0 > mv[mi][0]) || (mn1 > mv[mi][1]);
            mv[mi][0] = mn0; mv[mi][1] = mn1;

            uint32_t* Pw = Ps + w * 32 * 68;
            float ps0 = 0.f, ps1 = 0.f;
#pragma unroll
            for (int nt = 0; nt < 8; nt++) {
                float p0 = ex2(sc[mi][nt][0] - mn0);
                float p1 = ex2(sc[mi][nt][1] - mn0);
                float p2 = ex2(sc[mi][nt][2] - mn1);
                float p3 = ex2(sc[mi][nt][3] - mn1);
                ps0 += p0 + p1; ps1 += p2 + p3;
                Pw[(mi * 16 + r    ) * 68 + nt * 8 + 2 * c    ] = f2tf(p0);
                Pw[(mi * 16 + r    ) * 68 + nt * 8 + 2 * c + 1] = f2tf(p1);
                Pw[(mi * 16 + r + 8) * 68 + nt * 8 + 2 * c    ] = f2tf(p2);
                Pw[(mi * 16 + r + 8) * 68 + nt * 8 + 2 * c + 1] = f2tf(p3);
            }
            ps0 += __shfl_xor_sync(0xffffffff, ps0, 1);
            ps0 += __shfl_xor_sync(0xffffffff, ps0, 2);
            ps1 += __shfl_xor_sync(0xffffffff, ps1, 1);
            ps1 += __shfl_xor_sync(0xffffffff, ps1, 2);
            lv[mi][0] = lv[mi][0] * cor[mi][0] + ps0;
            lv[mi][1] = lv[mi][1] * cor[mi][1] + ps1;
        }

        if (__ballot_sync(0xffffffff, need_rescale)) {
#pragma unroll
            for (int mi = 0; mi < 2; mi++)
#pragma unroll
                for (int ne = 0; ne < 8; ne++) {
                    o[mi][ne][0] *= cor[mi][0]; o[mi][ne][1] *= cor[mi][0];
                    o[mi][ne][2] *= cor[mi][1]; o[mi][ne][3] *= cor[mi][1];
                }
        }

        __syncwarp();

        const uint32_t* Vb = Vs + (size_t)buf * 64 * 72;
#pragma unroll
        for (int k2 = 0; k2 < 8; k2++) {
            uint32_t pa0[4], pa1[4];
            ldsm4(pa0, ps_addr + ((k2 * 8) << 2));
            ldsm4(pa1, ps_addr + ((16 * 68 + k2 * 8) << 2));
#pragma unroll
            for (int ne = 0; ne < 8; ne++) {
                uint32_t bf2[2];
                bf2[0] = Vb[(k2 * 8 + c    ) * 72 + ne * 8 + r];
                bf2[1] = Vb[(k2 * 8 + c + 4) * 72 + ne * 8 + r];
                mma8(o[0][ne], pa0, bf2);
                mma8(o[1][ne], pa1, bf2);
            }
        }

        __syncthreads();
        if (ti + 2 < NT) cp_kv((ti + 2) * 64, buf);
    }

#pragma unroll
    for (int mi = 0; mi < 2; mi++) {
        const float inv0 = 1.f / lv[mi][0], inv1 = 1.f / lv[mi][1];
        const size_t ob = (size_t)(b * SS + s0 + w * 32 + mi * 16) * DD + h * EHD;
#pragma unroll
        for (int ne = 0; ne < 8; ne++) {
            *(float2*)&g_o[ob + (size_t)r * DD + ne * 8 + 2 * c] =
                make_float2(__uint_as_float(f2tf(o[mi][ne][0] * inv0)),
                            __uint_as_float(f2tf(o[mi][ne][1] * inv0)));
            *(float2*)&g_o[ob + (size_t)(r + 8) * DD + ne * 8 + 2 * c] =
                make_float2(__uint_as_float(f2tf(o[mi][ne][2] * inv1)),
                            __uint_as_float(f2tf(o[mi][ne][3] * inv1)));
        }
    }
}

// ---------------------------------------------------------------------------
extern "C" void kernel_launch(void* const* d_in, const int* in_sizes, int n_in,
                              void* d_out, int out_size)
{
    (void)in_sizes; (void)n_in; (void)out_size;
    const float* E  = (const float*)d_in[0];
    const float* WQ = (const float*)d_in[1];
    const float* WK = (const float*)d_in[2];
    const float* WV = (const float*)d_in[3];
    const float* WO = (const float*)d_in[4];
    const float* HQ = (const float*)d_in[5];
    const float* HK = (const float*)d_in[6];
    const float* HV = (const float*)d_in[7];
    float* out = (float*)d_out;

    float *wq, *wk, *wv, *q, *k, *v, *o;
    cudaGetSymbolAddress((void**)&wq, g_wq);
    cudaGetSymbolAddress((void**)&wk, g_wk);
    cudaGetSymbolAddress((void**)&wv, g_wv);
    cudaGetSymbolAddress((void**)&q,  g_q);
    cudaGetSymbolAddress((void**)&k,  g_k);
    cudaGetSymbolAddress((void**)&v,  g_v);
    cudaGetSymbolAddress((void**)&o,  g_o);

    cudaFuncSetAttribute(flash_tc, cudaFuncAttributeMaxDynamicSharedMemorySize,
                         FLASH_SMEM_BYTES);

    dim3 blk(128);

    // 1) Weff = HXcat @ WX (NN). A,B external -> cvt; C pre-rounded.
    GemmBatch gw;
    gw.A[0] = HQ; gw.B[0] = WQ; gw.C[0] = wq;
    gw.A[1] = HK; gw.B[1] = WK; gw.C[1] = wk;
    gw.A[2] = HV; gw.B[2] = WV; gw.C[2] = wv;
    gemm_tc<false, true, true, true><<<dim3(DD/128, DD/128, 3), blk>>>(gw, DD, DD, DD);

    // 2) q/k/v = E @ Weff^T (NT). A external -> cvt; B pre-rounded; C pre-rounded.
    GemmBatch ga;
    ga.A[0] = E; ga.B[0] = wq; ga.C[0] = q;
    ga.A[1] = E; ga.B[1] = wk; ga.C[1] = k;
    ga.A[2] = E; ga.B[2] = wv; ga.C[2] = v;
    gemm_tc<true, true, false, true><<<dim3(DD/128, MM/128, 3), blk>>>(ga, MM, DD, DD);

    // 3) attention (writes tf32-rounded o)
    flash_tc<<<dim3(SS/128, BB*HH), 128, FLASH_SMEM_BYTES>>>();

    // 4) out = o @ WO^T. A pre-rounded; B external -> cvt; C full fp32.
    GemmBatch go;
    go.A[0] = o; go.B[0] = WO; go.C[0] = out;
    go.A[1] = o; go.B[1] = WO; go.C[1] = out;
    go.A[2] = o; go.B[2] = WO; go.C[2] = out;
    gemm_tc<true, false, true, false><<<dim3(DD/128, MM/128, 1), blk>>>(go, MM, DD, DD);
}